// round 1
// baseline (speedup 1.0000x reference)
#include <cuda_runtime.h>
#include <math.h>

#define FFT_N 1024
#define NTH 256
// pad every 32 floats to break bank-conflict patterns on strided Stockham writes
#define PADI(i) ((i) + ((i) >> 5))
#define SMEM_LEN (FFT_N + (FFT_N >> 5))

__global__ __launch_bounds__(NTH) void dft1024_fft_kernel(
    const float* __restrict__ x, float2* __restrict__ out)
{
    __shared__ float sre[2][SMEM_LEN];
    __shared__ float sim[2][SMEM_LEN];

    const int t = threadIdx.x;
    const long long pair = blockIdx.x;
    const float* __restrict__ rowA = x + pair * (2 * FFT_N);
    const float* __restrict__ rowB = rowA + FFT_N;

    // Pack two real rows into one complex sequence: z = rowA + i*rowB
    #pragma unroll
    for (int r = 0; r < 4; r++) {
        int i = t + r * NTH;
        sre[0][PADI(i)] = rowA[i];
        sim[0][PADI(i)] = rowB[i];
    }
    __syncthreads();

    // Stockham autosort radix-4 FFT, 5 stages, forward (e^{-2*pi*i*nk/N})
    int cur = 0;
    #pragma unroll
    for (int s = 0; s < 5; s++) {
        const int Ns = 1 << (2 * s);
        const int j  = t;
        const int jm = j & (Ns - 1);

        float vr[4], vi[4];
        #pragma unroll
        for (int r = 0; r < 4; r++) {
            int idx = j + r * (FFT_N / 4);
            vr[r] = sre[cur][PADI(idx)];
            vi[r] = sim[cur][PADI(idx)];
        }

        if (s > 0) {
            float ang = (-6.283185307179586f) * (float)jm / (float)(4 * Ns);
            float s1, c1;
            sincosf(ang, &s1, &c1);
            float c2 = c1 * c1 - s1 * s1, s2 = 2.0f * c1 * s1;
            float c3 = c2 * c1 - s2 * s1, s3 = c2 * s1 + s2 * c1;
            float tr, ti;
            tr = vr[1] * c1 - vi[1] * s1; ti = vr[1] * s1 + vi[1] * c1; vr[1] = tr; vi[1] = ti;
            tr = vr[2] * c2 - vi[2] * s2; ti = vr[2] * s2 + vi[2] * c2; vr[2] = tr; vi[2] = ti;
            tr = vr[3] * c3 - vi[3] * s3; ti = vr[3] * s3 + vi[3] * c3; vr[3] = tr; vi[3] = ti;
        }

        // radix-4 butterfly (forward DFT of size 4)
        float t0r = vr[0] + vr[2], t0i = vi[0] + vi[2];
        float t1r = vr[0] - vr[2], t1i = vi[0] - vi[2];
        float t2r = vr[1] + vr[3], t2i = vi[1] + vi[3];
        float t3r = vr[1] - vr[3], t3i = vi[1] - vi[3];
        float o0r = t0r + t2r, o0i = t0i + t2i;
        float o2r = t0r - t2r, o2i = t0i - t2i;
        float o1r = t1r + t3i, o1i = t1i - t3r;   // t1 + (-i)*t3
        float o3r = t1r - t3i, o3i = t1i + t3r;   // t1 + ( i)*t3

        int idxD = ((j >> (2 * s)) << (2 * s + 2)) + jm;   // (j/Ns)*4*Ns + (j%Ns)
        int nxt = cur ^ 1;
        sre[nxt][PADI(idxD)]           = o0r; sim[nxt][PADI(idxD)]           = o0i;
        sre[nxt][PADI(idxD + Ns)]      = o1r; sim[nxt][PADI(idxD + Ns)]      = o1i;
        sre[nxt][PADI(idxD + 2 * Ns)]  = o2r; sim[nxt][PADI(idxD + 2 * Ns)]  = o2i;
        sre[nxt][PADI(idxD + 3 * Ns)]  = o3r; sim[nxt][PADI(idxD + 3 * Ns)]  = o3i;
        cur = nxt;
        __syncthreads();
    }

    // Unpack the two real spectra via conjugate symmetry and write interleaved
    float2* __restrict__ outA = out + pair * (2 * FFT_N);
    float2* __restrict__ outB = outA + FFT_N;
    #pragma unroll
    for (int r = 0; r < 4; r++) {
        int k  = t + r * NTH;
        int kn = (FFT_N - k) & (FFT_N - 1);
        float zr  = sre[cur][PADI(k)],  zi  = sim[cur][PADI(k)];
        float zr2 = sre[cur][PADI(kn)], zi2 = sim[cur][PADI(kn)];
        // Y_A[k] = 0.5*(Z[k] + conj(Z[N-k]))
        outA[k] = make_float2(0.5f * (zr + zr2), 0.5f * (zi - zi2));
        // Y_B[k] = -0.5i*(Z[k] - conj(Z[N-k]))
        outB[k] = make_float2(0.5f * (zi + zi2), 0.5f * (zr2 - zr));
    }
}

extern "C" void kernel_launch(void* const* d_in, const int* in_sizes, int n_in,
                              void* d_out, int out_size)
{
    const float* x = (const float*)d_in[0];
    // inputs: x [B, 1024], dft_real [1024,1024], dft_imag [1024,1024] (unused: FFT == DFT)
    int B = in_sizes[0] / FFT_N;   // 16384
    int pairs = B / 2;             // 8192 — two real rows per complex FFT
    dft1024_fft_kernel<<<pairs, NTH>>>(x, (float2*)d_out);
}

// round 5
// speedup vs baseline: 1.3051x; 1.3051x over previous
#include <cuda_runtime.h>

#define FFT_N 1024
#define PADI(i) ((i) + ((i) >> 5))
#define SLEN (FFT_N + (FFT_N >> 5))   // 1056 floats per array

__device__ __forceinline__ void cmul(float &ar, float &ai, float br, float bi) {
    float r = ar * br - ai * bi;
    float i = ar * bi + ai * br;
    ar = r; ai = i;
}

// forward 4-point DFT in place (W_4 = -i convention, matches e^{-2*pi*i/4})
__device__ __forceinline__ void dft4(float &r0, float &i0, float &r1, float &i1,
                                     float &r2, float &i2, float &r3, float &i3) {
    float t0r = r0 + r2, t0i = i0 + i2;
    float t1r = r0 - r2, t1i = i0 - i2;
    float t2r = r1 + r3, t2i = i1 + i3;
    float t3r = r1 - r3, t3i = i1 - i3;
    r0 = t0r + t2r; i0 = t0i + t2i;
    r2 = t0r - t2r; i2 = t0i - t2i;
    r1 = t1r + t3i; i1 = t1i - t3r;   // t1 + (-i)*t3
    r3 = t1r - t3i; i3 = t1i + t3r;   // t1 + ( i)*t3
}

// forward 16-point DFT in place. Input v[n] natural order.
// Output X[r] lands at slot perm(r) = 4*(r&3) + (r>>2) (self-inverse base-4 digit swap).
__device__ __forceinline__ void dft16(float *vr, float *vi) {
    #pragma unroll
    for (int m = 0; m < 4; m++)
        dft4(vr[m], vi[m], vr[m+4], vi[m+4], vr[m+8], vi[m+8], vr[m+12], vi[m+12]);

    const float C1 = 0.92387953251128674f;   // cos(pi/8)
    const float S1 = 0.38268343236508978f;   // sin(pi/8)
    const float R2 = 0.70710678118654752f;   // sqrt(2)/2
    // slot(m,q) = m + 4q gets * W_16^{m*q}
    cmul(vr[5],  vi[5],   C1, -S1);   // W^1
    cmul(vr[9],  vi[9],   R2, -R2);   // W^2
    cmul(vr[13], vi[13],  S1, -C1);   // W^3
    cmul(vr[6],  vi[6],   R2, -R2);   // W^2
    { float t = vr[10]; vr[10] = vi[10]; vi[10] = -t; }  // W^4 = -i
    cmul(vr[14], vi[14], -R2, -R2);   // W^6
    cmul(vr[7],  vi[7],   S1, -C1);   // W^3
    cmul(vr[11], vi[11], -R2, -R2);   // W^6
    cmul(vr[15], vi[15], -C1,  S1);   // W^9

    #pragma unroll
    for (int q = 0; q < 4; q++)
        dft4(vr[4*q], vi[4*q], vr[4*q+1], vi[4*q+1],
             vr[4*q+2], vi[4*q+2], vr[4*q+3], vi[4*q+3]);
}

__global__ __launch_bounds__(256) void dft1024_r16_kernel(
    const float* __restrict__ x,
    const float* __restrict__ dftr,
    const float* __restrict__ dfti,
    float2* __restrict__ out)
{
    __shared__ float sre[4][SLEN];
    __shared__ float sim[4][SLEN];

    const int u = threadIdx.x & 63;          // thread within one FFT group
    const int f = threadIdx.x >> 6;          // which of 4 FFTs in this block
    const int pair = blockIdx.x * 4 + f;     // row-pair index

    const float* __restrict__ rowA = x + (size_t)pair * (2 * FFT_N);
    const float* __restrict__ rowB = rowA + FFT_N;
    float* __restrict__ SR = sre[f];
    float* __restrict__ SI = sim[f];
    // Row 1 of the DFT matrices is an exact W_1024 twiddle table:
    // (dftr[1024+m], dfti[1024+m]) = e^{-2*pi*i*m/1024}
    const float* __restrict__ twr = dftr + FFT_N;
    const float* __restrict__ twi = dfti + FFT_N;

    float vr[16], vi[16];

    // ── Stage A: radix-16, Ns=1 (no twiddles), reads straight from global ──
    #pragma unroll
    for (int r = 0; r < 16; r++) {
        vr[r] = rowA[u + 64 * r];   // z = rowA + i*rowB (two real rows packed)
        vi[r] = rowB[u + 64 * r];
    }
    dft16(vr, vi);
    #pragma unroll
    for (int r = 0; r < 16; r++) {
        int s = 4 * (r & 3) + (r >> 2);      // slot holding X[r]
        SR[PADI(16 * u + r)] = vr[s];
        SI[PADI(16 * u + r)] = vi[s];
    }
    __syncthreads();

    // ── Stage B: radix-16, Ns=16 ──
    #pragma unroll
    for (int r = 0; r < 16; r++) {
        vr[r] = SR[PADI(u + 64 * r)];
        vi[r] = SI[PADI(u + 64 * r)];
    }
    {
        int jm = u & 15;
        float wr = twr[4 * jm], wi = twi[4 * jm];  // W_256^{jm} = W_1024^{4*jm}
        float cr = wr, ci = wi;
        #pragma unroll
        for (int r = 1; r < 16; r++) {
            cmul(vr[r], vi[r], cr, ci);            // v[r] *= W_256^{jm*r}
            if (r < 15) cmul(cr, ci, wr, wi);
        }
    }
    dft16(vr, vi);
    __syncthreads();   // all reads complete before overwriting the buffer
    {
        int base = ((u >> 4) << 8) + (u & 15);     // (j/16)*256 + j%16
        #pragma unroll
        for (int r = 0; r < 16; r++) {
            int s = 4 * (r & 3) + (r >> 2);
            SR[PADI(base + 16 * r)] = vr[s];
            SI[PADI(base + 16 * r)] = vi[s];
        }
    }
    __syncthreads();

    // ── Stage C: radix-4, Ns=256 — per-thread in-place (read set == write set) ──
    #pragma unroll
    for (int b = 0; b < 4; b++) {
        int j = u + 64 * b;
        float ar = SR[PADI(j)],        ai = SI[PADI(j)];
        float br = SR[PADI(j + 256)],  bi = SI[PADI(j + 256)];
        float cr = SR[PADI(j + 512)],  ci = SI[PADI(j + 512)];
        float er = SR[PADI(j + 768)],  ei = SI[PADI(j + 768)];

        float w1r = twr[j], w1i = twi[j];                   // W_1024^{j}
        float w2r = w1r * w1r - w1i * w1i, w2i = 2.0f * w1r * w1i;
        float w3r = w2r * w1r - w2i * w1i, w3i = w2r * w1i + w2i * w1r;
        cmul(br, bi, w1r, w1i);
        cmul(cr, ci, w2r, w2i);
        cmul(er, ei, w3r, w3i);

        float t0r = ar + cr, t0i = ai + ci;
        float t1r = ar - cr, t1i = ai - ci;
        float t2r = br + er, t2i = bi + ei;
        float t3r = br - er, t3i = bi - ei;
        SR[PADI(j)]       = t0r + t2r;  SI[PADI(j)]       = t0i + t2i;
        SR[PADI(j + 512)] = t0r - t2r;  SI[PADI(j + 512)] = t0i - t2i;
        SR[PADI(j + 256)] = t1r + t3i;  SI[PADI(j + 256)] = t1i - t3r;
        SR[PADI(j + 768)] = t1r - t3i;  SI[PADI(j + 768)] = t1i + t3r;
    }
    __syncthreads();

    // ── Unpack two real spectra via conjugate symmetry, write interleaved ──
    float2* __restrict__ outA = out + (size_t)pair * (2 * FFT_N);
    float2* __restrict__ outB = outA + FFT_N;
    #pragma unroll
    for (int r = 0; r < 16; r++) {
        int k  = u + 64 * r;
        int kn = (FFT_N - k) & (FFT_N - 1);
        float zr = SR[PADI(k)],  zi = SI[PADI(k)];
        float yr = SR[PADI(kn)], yi = SI[PADI(kn)];
        outA[k] = make_float2(0.5f * (zr + yr), 0.5f * (zi - yi));
        outB[k] = make_float2(0.5f * (zi + yi), 0.5f * (yr - zr));
    }
}

extern "C" void kernel_launch(void* const* d_in, const int* in_sizes, int n_in,
                              void* d_out, int out_size)
{
    const float* x    = (const float*)d_in[0];
    const float* dftr = (const float*)d_in[1];
    const float* dfti = (const float*)d_in[2];
    int B = in_sizes[0] / FFT_N;     // 16384 rows
    int pairs = B / 2;               // 8192 complex FFTs (2 real rows each)
    int blocks = pairs / 4;          // 4 FFTs per 256-thread block
    dft1024_r16_kernel<<<blocks, 256>>>(x, dftr, dfti, (float2*)d_out);
}